// round 1
// baseline (speedup 1.0000x reference)
#include <cuda_runtime.h>
#include <math.h>

#define NN 60000
#define EE 300000
#define AA 8000
#define GG 256
#define DD 128
#define HH 8
#define CC 16
#define RBFD 16
#define SBFD 112
#define LLAYERS 3

// ---------------- scratch (device globals; no allocation allowed) ----------------
__device__ float g_cur [NN*DD];
__device__ float g_hbuf[NN*DD];
__device__ float g_t1  [NN*DD];
__device__ float g_t2  [NN*DD];
__device__ float g_q   [NN*DD];
__device__ float g_k   [NN*DD];
__device__ float g_v   [NN*DD];
__device__ float g_eaA [EE*DD];
__device__ float g_eaB [EE*DD];
__device__ float g_atoms [AA*DD];
__device__ float g_atoms2[AA*DD];
__device__ float g_a1  [AA*DD];
__device__ float g_a2  [AA*DD];
__device__ float g_logit[EE*HH];
__device__ unsigned g_m[NN*HH];
__device__ float g_den [NN*HH];
__device__ float g_results[AA];
__device__ float g_gstat[5*GG];   // [0:G)=sum [G:2G)=cnt [2G:3G)=mean [3G:4G)=var [4G:5G)=rstd

// ---------------- helpers ----------------
__device__ __forceinline__ float siluf(float v){ return v * (1.f / (1.f + __expf(-v))); }
__device__ __forceinline__ unsigned f2o(float f){ unsigned u=__float_as_uint(f); return (u&0x80000000u)? ~u : (u|0x80000000u); }
__device__ __forceinline__ float o2f(unsigned u){ return (u&0x80000000u)? __uint_as_float(u^0x80000000u) : __uint_as_float(~u); }

// ---------------- tiled SGEMM: C[M,128] = epi(A'[M,K] @ W[K,128] + bias) ----------------
// A'[m,:] = A[gidx[m],:] if GATHER. BM=128, BN=128, BK=16, 256 threads, 8x8 microtile.
template<int ACT, bool GATHER, bool HASRES>
__global__ __launch_bounds__(256)
void gemm128(const float* __restrict__ A, const float* __restrict__ W,
             const float* __restrict__ bias, const float* __restrict__ res,
             const int* __restrict__ gidx, float* __restrict__ C,
             int M, int K)
{
    __shared__ float As[16][132];
    __shared__ float Ws[16][128];
    const int tid = threadIdx.x;
    const int ty = tid >> 4, tx = tid & 15;
    const int row0 = blockIdx.x * 128;

    float acc[8][8];
    #pragma unroll
    for (int i=0;i<8;i++)
        #pragma unroll
        for(int j=0;j<8;j++) acc[i][j]=0.f;

    for (int k0 = 0; k0 < K; k0 += 16) {
        #pragma unroll
        for (int i = 0; i < 2; i++) {
            int f4 = tid + i*256;              // 0..511
            int r  = f4 >> 2;                  // tile row
            int kc = (f4 & 3) << 2;            // k offset (0,4,8,12)
            int grow = row0 + r;
            float4 vv = make_float4(0.f,0.f,0.f,0.f);
            if (grow < M) {
                int arow = GATHER ? __ldg(gidx + grow) : grow;
                vv = *reinterpret_cast<const float4*>(A + (size_t)arow*K + (k0+kc));
            }
            As[kc+0][r]=vv.x; As[kc+1][r]=vv.y; As[kc+2][r]=vv.z; As[kc+3][r]=vv.w;
        }
        #pragma unroll
        for (int i = 0; i < 2; i++) {
            int f4 = tid + i*256;
            int kr = f4 >> 5;                  // 0..15
            int nc = (f4 & 31) << 2;
            *reinterpret_cast<float4*>(&Ws[kr][nc]) =
                *reinterpret_cast<const float4*>(W + (size_t)(k0+kr)*128 + nc);
        }
        __syncthreads();
        #pragma unroll
        for (int kk = 0; kk < 16; kk++) {
            float4 a0 = *reinterpret_cast<const float4*>(&As[kk][ty*8]);
            float4 a1 = *reinterpret_cast<const float4*>(&As[kk][ty*8+4]);
            float4 b0 = *reinterpret_cast<const float4*>(&Ws[kk][tx*8]);
            float4 b1 = *reinterpret_cast<const float4*>(&Ws[kk][tx*8+4]);
            float ra[8] = {a0.x,a0.y,a0.z,a0.w,a1.x,a1.y,a1.z,a1.w};
            float rb[8] = {b0.x,b0.y,b0.z,b0.w,b1.x,b1.y,b1.z,b1.w};
            #pragma unroll
            for(int i=0;i<8;i++)
                #pragma unroll
                for(int j=0;j<8;j++)
                    acc[i][j] = fmaf(ra[i], rb[j], acc[i][j]);
        }
        __syncthreads();
    }
    #pragma unroll
    for (int i=0;i<8;i++){
        int gr = row0 + ty*8 + i;
        if (gr >= M) break;
        #pragma unroll
        for (int j=0;j<8;j+=4){
            int c = tx*8 + j;
            float o[4];
            #pragma unroll
            for (int q=0;q<4;q++){
                float val = acc[i][j+q];
                if (bias) val += __ldg(bias + c + q);
                if (ACT==1) val = siluf(val);
                if (HASRES) val += res[(size_t)gr*128 + c + q];
                o[q]=val;
            }
            *reinterpret_cast<float4*>(C + (size_t)gr*128 + c) =
                make_float4(o[0],o[1],o[2],o[3]);
        }
    }
}

// ---------------- scatter rows: dst[idx[n],:] += src[n,:] ----------------
__global__ void scatter_rows_kernel(const float* __restrict__ src, const int* __restrict__ idx,
                                    float* __restrict__ dstb, int nrows)
{
    int i = blockIdx.x*blockDim.x + threadIdx.x;
    if (i >= nrows*32) return;
    int n = i >> 5, c4 = i & 31;
    int a = __ldg(idx + n);
    float4 v = *reinterpret_cast<const float4*>(src + (size_t)n*128 + c4*4);
    float* d = dstb + (size_t)a*128 + c4*4;
    atomicAdd(d+0,v.x); atomicAdd(d+1,v.y); atomicAdd(d+2,v.z); atomicAdd(d+3,v.w);
}

// ---------------- rbf gate: h[n,c] *= (rbf[n,:] @ W[:,c]) ----------------
__global__ void gate_mul_kernel(float* __restrict__ h, const float* __restrict__ rbf,
                                const float* __restrict__ W)
{
    __shared__ float Ws[RBFD][DD];
    for (int t=threadIdx.x; t<RBFD*DD; t+=256) ((float*)Ws)[t] = W[t];
    __syncthreads();
    int c   = threadIdx.x & 127;
    int sub = threadIdx.x >> 7;
    int n0  = blockIdx.x*128;
    int nend = min(n0+128, NN);
    for (int n = n0+sub; n < nend; n += 2){
        const float* r = rbf + (size_t)n*RBFD;
        float g = 0.f;
        #pragma unroll
        for (int kk=0;kk<RBFD;kk++) g = fmaf(__ldg(r+kk), Ws[kk][c], g);
        h[(size_t)n*DD+c] *= g;
    }
}

// ---------------- readout gate + scatter: atoms[idx[n],c] += h[n,c]*gate ----------------
__global__ void gate_scatter_kernel(const float* __restrict__ h, const float* __restrict__ rbf,
                                    const float* __restrict__ W, const int* __restrict__ idx,
                                    float* __restrict__ atoms)
{
    __shared__ float Ws[RBFD][DD];
    for (int t=threadIdx.x; t<RBFD*DD; t+=256) ((float*)Ws)[t] = W[t];
    __syncthreads();
    int c   = threadIdx.x & 127;
    int sub = threadIdx.x >> 7;
    int n0  = blockIdx.x*128;
    int nend = min(n0+128, NN);
    for (int n = n0+sub; n < nend; n += 2){
        const float* r = rbf + (size_t)n*RBFD;
        float g = 0.f;
        #pragma unroll
        for (int kk=0;kk<RBFD;kk++) g = fmaf(__ldg(r+kk), Ws[kk][c], g);
        atomicAdd(&atoms[(size_t)__ldg(idx+n)*DD + c], h[(size_t)n*DD+c]*g);
    }
}

// ---------------- attention: logits + running max ----------------
__global__ void logit_kernel(const float* __restrict__ q, const float* __restrict__ k,
                             const float* __restrict__ ek, const int* __restrict__ src,
                             const int* __restrict__ dst, float* __restrict__ logit,
                             unsigned* __restrict__ mOrd)
{
    int i = blockIdx.x*blockDim.x + threadIdx.x;
    if (i >= EE*HH) return;
    int e = i >> 3, h = i & 7;
    int s = __ldg(src+e), d = __ldg(dst+e);
    const float4* qp = (const float4*)(q  + (size_t)d*DD + h*CC);
    const float4* kp = (const float4*)(k  + (size_t)s*DD + h*CC);
    const float4* ep = (const float4*)(ek + (size_t)e*DD + h*CC);
    float acc = 0.f;
    #pragma unroll
    for (int j=0;j<4;j++){
        float4 a=qp[j], b=kp[j], c=ep[j];
        acc += a.x*(b.x+c.x)+a.y*(b.y+c.y)+a.z*(b.z+c.z)+a.w*(b.w+c.w);
    }
    acc *= 0.25f;              // 1/sqrt(16)
    logit[i] = acc;
    atomicMax(&mOrd[(size_t)d*HH+h], f2o(acc));
}

// ---------------- attention: exp + denominator ----------------
__global__ void exp_kernel(const int* __restrict__ dst, float* __restrict__ logit,
                           const unsigned* __restrict__ mOrd, float* __restrict__ den)
{
    int i = blockIdx.x*blockDim.x + threadIdx.x;
    if (i >= EE*HH) return;
    int e = i >> 3, h = i & 7;
    int d = __ldg(dst+e);
    float m  = o2f(mOrd[(size_t)d*HH+h]);
    float ex = __expf(logit[i] - m);
    logit[i] = ex;
    atomicAdd(&den[(size_t)d*HH+h], ex);
}

// ---------------- attention: weighted message scatter ----------------
__global__ void msg_kernel(const float* __restrict__ v, const float* __restrict__ ek,
                           const float* __restrict__ sw, const float* __restrict__ ex,
                           const float* __restrict__ den, const int* __restrict__ src,
                           const int* __restrict__ dst, float* __restrict__ hout)
{
    int i = blockIdx.x*blockDim.x + threadIdx.x;
    if (i >= EE*32) return;
    int e = i >> 5, c4 = i & 31, h = c4 >> 2;
    int sN = __ldg(src+e), dN = __ldg(dst+e);
    float alpha = __ldg(ex + (size_t)e*HH + h) / (__ldg(den + (size_t)dN*HH + h) + 1e-16f);
    float4 vv = *(const float4*)(v  + (size_t)sN*DD + c4*4);
    float4 ee = *(const float4*)(ek + (size_t)e*DD  + c4*4);
    float4 ww = *(const float4*)(sw + (size_t)e*DD  + c4*4);
    float* o = hout + (size_t)dN*DD + c4*4;
    atomicAdd(o+0, (vv.x+ee.x)*alpha*ww.x);
    atomicAdd(o+1, (vv.y+ee.y)*alpha*ww.y);
    atomicAdd(o+2, (vv.z+ee.z)*alpha*ww.z);
    atomicAdd(o+3, (vv.w+ee.w)*alpha*ww.w);
}

// ---------------- graph norm ----------------
__global__ void gn_pass1_kernel(const float* __restrict__ h, const int* __restrict__ batch,
                                float* __restrict__ gstat)
{
    int gi = blockIdx.x*blockDim.x + threadIdx.x;
    int n = gi >> 5, lane = gi & 31;
    if (n >= NN) return;
    float4 v = *reinterpret_cast<const float4*>(h + (size_t)n*128 + lane*4);
    float s = v.x+v.y+v.z+v.w;
    #pragma unroll
    for(int o=16;o;o>>=1) s += __shfl_xor_sync(0xffffffffu, s, o);
    if (!lane){
        int g = __ldg(batch+n);
        atomicAdd(&gstat[g], s);
        atomicAdd(&gstat[GG+g], 1.f);
    }
}
__global__ void gn_mean_kernel(float* gstat)
{
    int g = threadIdx.x;
    if (g >= GG) return;
    float cnt = gstat[GG+g]*128.f;
    gstat[2*GG+g] = (cnt > 0.f) ? gstat[g]/cnt : 0.f;
}
__global__ void gn_pass2_kernel(const float* __restrict__ h, const int* __restrict__ batch,
                                float* __restrict__ gstat)
{
    int gi = blockIdx.x*blockDim.x + threadIdx.x;
    int n = gi >> 5, lane = gi & 31;
    if (n >= NN) return;
    int g = __ldg(batch+n);
    float mean = gstat[2*GG+g];
    float4 v = *reinterpret_cast<const float4*>(h + (size_t)n*128 + lane*4);
    float a=v.x-mean, b=v.y-mean, c=v.z-mean, d=v.w-mean;
    float s = a*a+b*b+c*c+d*d;
    #pragma unroll
    for(int o=16;o;o>>=1) s += __shfl_xor_sync(0xffffffffu, s, o);
    if (!lane) atomicAdd(&gstat[3*GG+g], s);
}
__global__ void gn_rstd_kernel(float* gstat)
{
    int g = threadIdx.x;
    if (g >= GG) return;
    float cnt = gstat[GG+g]*128.f;
    float var = (cnt > 0.f) ? gstat[3*GG+g]/cnt : 0.f;
    gstat[4*GG+g] = rsqrtf(var + 1e-8f);
}
__global__ void gn_apply_kernel(float* __restrict__ h, const int* __restrict__ batch,
                                const float* __restrict__ gstat)
{
    int i = blockIdx.x*blockDim.x + threadIdx.x;
    if (i >= NN*32) return;
    int n = i >> 5;
    int g = __ldg(batch+n);
    float mean = gstat[2*GG+g], rstd = gstat[4*GG+g];
    float4 v = *reinterpret_cast<const float4*>(h + (size_t)n*128 + (i&31)*4);
    v.x=(v.x-mean)*rstd; v.y=(v.y-mean)*rstd; v.z=(v.z-mean)*rstd; v.w=(v.w-mean)*rstd;
    *reinterpret_cast<float4*>(h + (size_t)n*128 + (i&31)*4) = v;
}

// ---------------- readout final dot: results[a] += a2[a,:]@w3 + b3 ----------------
__global__ void readout_dot_kernel(const float* __restrict__ a2, const float* __restrict__ w3,
                                   const float* __restrict__ b3, float* __restrict__ results)
{
    int gi = blockIdx.x*blockDim.x + threadIdx.x;
    int a = gi >> 5, lane = gi & 31;
    if (a >= AA) return;
    float4 x = *(const float4*)(a2 + (size_t)a*128 + lane*4);
    float4 w = *(const float4*)(w3 + lane*4);
    float s = x.x*w.x + x.y*w.y + x.z*w.z + x.w*w.w;
    #pragma unroll
    for(int o=16;o;o>>=1) s += __shfl_xor_sync(0xffffffffu, s, o);
    if (!lane) results[a] += s + __ldg(b3);
}

// ---------------- final: out[g] = sum_a results[a] / 3 ----------------
__global__ void final_kernel(const float* __restrict__ results, const int* __restrict__ atom_batch,
                             float* __restrict__ out)
{
    int a = blockIdx.x*blockDim.x + threadIdx.x;
    if (a < AA) atomicAdd(&out[__ldg(atom_batch+a)], results[a]*(1.f/3.f));
}

// =======================================================================
extern "C" void kernel_launch(void* const* d_in, const int* in_sizes, int n_in,
                              void* d_out, int out_size)
{
    cudaStream_t s = 0;
    const float* x            = (const float*)d_in[0];
    const float* node_rbf     = (const float*)d_in[1];
    const float* edge_sbf     = (const float*)d_in[2];
    const int*   edge_index   = (const int*)  d_in[3];
    const int*   srcp = edge_index;
    const int*   dstp = edge_index + EE;
    const int*   pair_atom_idx= (const int*)  d_in[4];
    const int*   edge_index_0 = (const int*)  d_in[5];
    const int*   atom_batch   = (const int*)  d_in[6];
    const int*   batch        = (const int*)  d_in[7];
    const float* edgenn_w1    = (const float*)d_in[8];
    const float* edgenn_b1    = (const float*)d_in[9];
    const float* edgenn_w2    = (const float*)d_in[10];
    const float* edgenn_b2    = (const float*)d_in[11];
    const float* conv_wq      = (const float*)d_in[12];
    const float* conv_wk      = (const float*)d_in[13];
    const float* conv_wv      = (const float*)d_in[14];
    const float* conv_we      = (const float*)d_in[15];
    const float* conv_wsbf    = (const float*)d_in[16];
    const float* conv_bsbf    = (const float*)d_in[17];
    const float* conv_wrbf    = (const float*)d_in[18];
    const float* dense_w      = (const float*)d_in[19];
    const float* dense_b      = (const float*)d_in[20];
    const float* bf_w         = (const float*)d_in[21];
    const float* bf_b         = (const float*)d_in[22];
    const float* af_w         = (const float*)d_in[23];
    const float* af_b         = (const float*)d_in[24];
    const float* read_wrbf    = (const float*)d_in[25];
    const float* read_w1      = (const float*)d_in[26];
    const float* read_b1      = (const float*)d_in[27];
    const float* read_w2      = (const float*)d_in[28];
    const float* read_b2      = (const float*)d_in[29];
    const float* read_w3      = (const float*)d_in[30];
    const float* read_b3      = (const float*)d_in[31];

    float *cur_w, *hbuf, *t1, *t2, *q, *k_, *v_, *eaA, *eaB;
    float *atoms, *atoms2, *a1, *a2, *logit, *den, *results, *gstat;
    unsigned* mOrd;
    cudaGetSymbolAddress((void**)&cur_w,  g_cur);
    cudaGetSymbolAddress((void**)&hbuf,   g_hbuf);
    cudaGetSymbolAddress((void**)&t1,     g_t1);
    cudaGetSymbolAddress((void**)&t2,     g_t2);
    cudaGetSymbolAddress((void**)&q,      g_q);
    cudaGetSymbolAddress((void**)&k_,     g_k);
    cudaGetSymbolAddress((void**)&v_,     g_v);
    cudaGetSymbolAddress((void**)&eaA,    g_eaA);
    cudaGetSymbolAddress((void**)&eaB,    g_eaB);
    cudaGetSymbolAddress((void**)&atoms,  g_atoms);
    cudaGetSymbolAddress((void**)&atoms2, g_atoms2);
    cudaGetSymbolAddress((void**)&a1,     g_a1);
    cudaGetSymbolAddress((void**)&a2,     g_a2);
    cudaGetSymbolAddress((void**)&logit,  g_logit);
    cudaGetSymbolAddress((void**)&mOrd,   g_m);
    cudaGetSymbolAddress((void**)&den,    g_den);
    cudaGetSymbolAddress((void**)&results,g_results);
    cudaGetSymbolAddress((void**)&gstat,  g_gstat);

    auto gemmL = [&](const float* A, const float* Wp, const float* bp, const float* rp,
                     const int* gi, float* Cp, int M, int K, int act){
        dim3 gr((M+127)/128);
        if (gi)              gemm128<1,true ,false><<<gr,256,0,s>>>(A,Wp,bp,rp,gi,Cp,M,K);
        else if (act && rp)  gemm128<1,false,true ><<<gr,256,0,s>>>(A,Wp,bp,rp,gi,Cp,M,K);
        else if (act)        gemm128<1,false,false><<<gr,256,0,s>>>(A,Wp,bp,rp,gi,Cp,M,K);
        else                 gemm128<0,false,false><<<gr,256,0,s>>>(A,Wp,bp,rp,gi,Cp,M,K);
    };

    auto readout = [&](int i, const float* h){
        cudaMemsetAsync(atoms2, 0, (size_t)AA*DD*4, s);
        gate_scatter_kernel<<<(NN+127)/128, 256, 0, s>>>(
            h, node_rbf, read_wrbf + (size_t)i*RBFD*DD, edge_index_0, atoms2);
        gemmL(atoms2, read_w1 + (size_t)i*DD*DD, read_b1 + (size_t)i*DD, nullptr, nullptr, a1, AA, DD, 1);
        gemmL(a1,     read_w2 + (size_t)i*DD*DD, read_b2 + (size_t)i*DD, nullptr, nullptr, a2, AA, DD, 1);
        readout_dot_kernel<<<(AA*32+255)/256, 256, 0, s>>>(
            a2, read_w3 + (size_t)i*DD, read_b3 + i, results);
    };

    // ---- init ----
    cudaMemsetAsync(results, 0, (size_t)AA*4, s);
    readout(0, x);
    const float* cur = x;

    for (int i = 0; i < LLAYERS; i++){
        size_t wDD  = (size_t)i*DD*DD;
        // atoms_rep = segsum(cur, edge_index_0)
        cudaMemsetAsync(atoms, 0, (size_t)AA*DD*4, s);
        scatter_rows_kernel<<<(NN*32+255)/256, 256, 0, s>>>(cur, edge_index_0, atoms, NN);
        // ea = silu(atoms[pair]@w1+b1) @ w2 + b2
        gemmL(atoms, edgenn_w1 + wDD, edgenn_b1 + (size_t)i*DD, nullptr, pair_atom_idx, eaA, EE, DD, 1);
        gemmL(eaA,   edgenn_w2 + wDD, edgenn_b2 + (size_t)i*DD, nullptr, nullptr,       eaB, EE, DD, 0);
        // q,k,v
        gemmL(cur, conv_wq + wDD, nullptr, nullptr, nullptr, q,  NN, DD, 0);
        gemmL(cur, conv_wk + wDD, nullptr, nullptr, nullptr, k_, NN, DD, 0);
        gemmL(cur, conv_wv + wDD, nullptr, nullptr, nullptr, v_, NN, DD, 0);
        // ek = ea @ we   (overwrites eaA)
        gemmL(eaB, conv_we + wDD, nullptr, nullptr, nullptr, eaA, EE, DD, 0);
        // sw = edge_sbf @ wsbf + bsbf   (overwrites eaB)
        gemmL(edge_sbf, conv_wsbf + (size_t)i*SBFD*DD, conv_bsbf + (size_t)i*DD,
              nullptr, nullptr, eaB, EE, SBFD, 0);
        // attention softmax over dst
        cudaMemsetAsync(mOrd, 0, (size_t)NN*HH*4, s);
        cudaMemsetAsync(den,  0, (size_t)NN*HH*4, s);
        logit_kernel<<<(EE*HH+255)/256, 256, 0, s>>>(q, k_, eaA, srcp, dstp, logit, mOrd);
        exp_kernel  <<<(EE*HH+255)/256, 256, 0, s>>>(dstp, logit, mOrd, den);
        cudaMemsetAsync(hbuf, 0, (size_t)NN*DD*4, s);
        msg_kernel  <<<(EE*32+255)/256, 256, 0, s>>>(v_, eaA, eaB, logit, den, srcp, dstp, hbuf);
        // rbf gate
        gate_mul_kernel<<<(NN+127)/128, 256, 0, s>>>(hbuf, node_rbf, conv_wrbf + (size_t)i*RBFD*DD);
        // graph norm
        cudaMemsetAsync(gstat, 0, 5*GG*4, s);
        gn_pass1_kernel<<<(NN*32+255)/256, 256, 0, s>>>(hbuf, batch, gstat);
        gn_mean_kernel <<<1, GG, 0, s>>>(gstat);
        gn_pass2_kernel<<<(NN*32+255)/256, 256, 0, s>>>(hbuf, batch, gstat);
        gn_rstd_kernel <<<1, GG, 0, s>>>(gstat);
        gn_apply_kernel<<<(NN*32+255)/256, 256, 0, s>>>(hbuf, batch, gstat);
        // bf residual block: t2 = hbuf + silu(silu(hbuf@w0+b0)@w1+b1)
        gemmL(hbuf, bf_w + (size_t)i*2*DD*DD,          bf_b + (size_t)i*2*DD,      nullptr, nullptr, t1, NN, DD, 1);
        gemmL(t1,   bf_w + (size_t)i*2*DD*DD + DD*DD,  bf_b + (size_t)i*2*DD + DD, hbuf,    nullptr, t2, NN, DD, 1);
        // dense + residual(cur): t1 = silu(t2@dw+db) + cur
        gemmL(t2, dense_w + wDD, dense_b + (size_t)i*DD, cur, nullptr, t1, NN, DD, 1);
        // af block 1: t2 = t1 + silu(silu(t1@a0+b0)@a1+b1)   (q reused as scratch)
        gemmL(t1, af_w + (size_t)i*4*DD*DD,           af_b + (size_t)i*4*DD,        nullptr, nullptr, q,  NN, DD, 1);
        gemmL(q,  af_w + (size_t)i*4*DD*DD + 1*DD*DD, af_b + (size_t)i*4*DD + DD,   t1,      nullptr, t2, NN, DD, 1);
        // af block 2: cur_w = t2 + silu(silu(t2@a2+b2)@a3+b3)
        gemmL(t2, af_w + (size_t)i*4*DD*DD + 2*DD*DD, af_b + (size_t)i*4*DD + 2*DD, nullptr, nullptr, q,     NN, DD, 1);
        gemmL(q,  af_w + (size_t)i*4*DD*DD + 3*DD*DD, af_b + (size_t)i*4*DD + 3*DD, t2,      nullptr, cur_w, NN, DD, 1);
        cur = cur_w;
        readout(i+1, cur);
    }

    // ---- final reduce to graphs ----
    cudaMemsetAsync(d_out, 0, (size_t)GG*4, s);
    final_kernel<<<(AA+255)/256, 256, 0, s>>>(results, atom_batch, (float*)d_out);
}